// round 1
// baseline (speedup 1.0000x reference)
#include <cuda_runtime.h>

// TransducerBeamSearcher: persistent single-kernel greedy transducer decode.
// B=32, T=1000, H=640, V=5000. One kernel launch, software grid barrier.

constexpr int kB = 32;
constexpr int kT = 1000;
constexpr int kH = 640;
constexpr int kV = 5000;
constexpr int kG = 2560;   // 4*H

constexpr int NBLK = 148;  // <= SM count on GB300 -> all blocks co-resident
constexpr int NTHR = 256;

// Phase A (logits) tiling: 2 batch-groups x 20 v-chunks(256) x 16 h-splits(40) = 640 tiles
constexpr int HS_A = 16, HCH_A = 40;
constexpr int VCH_A = 20, VW_A = 256;
constexpr int TILES_A = 2 * VCH_A * HS_A;

// Phase C1 (LSTM gemm) tiling: inner dim 1280 ([x;h]); 2 bg x 10 j-chunks(256) x 32 h-splits(40) = 640
constexpr int HS_C = 32, HCH_C = 40;
constexpr int JCH_C = 10, JW_C = 256;
constexpr int TILES_C = 2 * JCH_C * HS_C;

// Scratch (device globals; no allocations allowed)
__device__ __align__(16) float d_part[(size_t)HS_A * kB * kV];      // 10.24 MB logits partials
__device__ __align__(16) float d_gpart[(size_t)HS_C * kB * kH * 4]; // 10.49 MB gate partials (4 gates interleaved)
__device__ __align__(16) float d_joint[kB * kH];
__device__ __align__(16) float d_h[kB * kH];
__device__ __align__(16) float d_c[kB * kH];
__device__ float d_scores[kB];
__device__ int d_tok[kB];
__device__ int d_newtok[kB];
__device__ int d_updf[kB];
__device__ unsigned g_count = 0;
__device__ unsigned g_gen = 0;   // monotonic across graph replays (wrap-safe)

__device__ __forceinline__ void grid_barrier() {
    __syncthreads();
    if (threadIdx.x == 0) {
        __threadfence();
        unsigned my = atomicAdd(&g_gen, 0u);   // stable: gen only moves after ALL arrive here
        if (atomicAdd(&g_count, 1u) == (unsigned)(NBLK - 1)) {
            atomicExch(&g_count, 0u);
            __threadfence();
            atomicAdd(&g_gen, 1u);
        } else {
            while (atomicAdd(&g_gen, 0u) == my) { __nanosleep(60); }
        }
        __threadfence();
    }
    __syncthreads();
}

// ---------------- Phase A: partial logits  joint[b,:] @ Wc ----------------
__device__ void phaseA(const float* __restrict__ Wc, float (*s_tile)[16]) {
    for (int tt = blockIdx.x; tt < TILES_A; tt += NBLK) {
        int hs  = tt & (HS_A - 1);
        int vch = (tt >> 4) % VCH_A;
        int bg  = tt / (HS_A * VCH_A);
        int hbase = hs * HCH_A;
        int v = vch * VW_A + threadIdx.x;

        for (int idx = threadIdx.x; idx < HCH_A * 16; idx += NTHR) {
            int hh = idx >> 4, bb = idx & 15;
            s_tile[hh][bb] = d_joint[(bg * 16 + bb) * kH + hbase + hh];
        }
        __syncthreads();

        if (v < kV) {
            float acc[16];
#pragma unroll
            for (int i = 0; i < 16; i++) acc[i] = 0.f;
            const float* wp = Wc + (size_t)hbase * kV + v;
#pragma unroll 4
            for (int hh = 0; hh < HCH_A; ++hh) {
                float w = wp[0]; wp += kV;
#pragma unroll
                for (int bb = 0; bb < 16; ++bb) acc[bb] += s_tile[hh][bb] * w;
            }
#pragma unroll
            for (int bb = 0; bb < 16; ++bb)
                d_part[((size_t)(hs * kB + bg * 16 + bb)) * kV + v] = acc[bb];
        }
        __syncthreads();
    }
}

// ---------------- Phase B: per-row reduce + argmax + lse + state decision ----------------
__device__ void phaseB(int t, const float* __restrict__ bc, float* __restrict__ out,
                       float* s_red, int* s_redi) {
    int b = blockIdx.x;
    if (b >= kB) return;
    int tid = threadIdx.x;

    float lv[20];
    float lmax = -1e30f;
    int lidx = 0x7fffffff;
#pragma unroll
    for (int k2 = 0; k2 < 5; k2++) {
        int v = 4 * tid + 1024 * k2;
        float4 s;
        if (v < kV) {
            s = *(const float4*)&bc[v];
#pragma unroll
            for (int hs = 0; hs < HS_A; hs++) {
                float4 p = *(const float4*)&d_part[((size_t)(hs * kB + b)) * kV + v];
                s.x += p.x; s.y += p.y; s.z += p.z; s.w += p.w;
            }
        } else {
            s.x = s.y = s.z = s.w = -1e30f;
        }
        lv[4 * k2 + 0] = s.x; lv[4 * k2 + 1] = s.y;
        lv[4 * k2 + 2] = s.z; lv[4 * k2 + 3] = s.w;
        if (s.x > lmax) { lmax = s.x; lidx = v; }
        if (s.y > lmax) { lmax = s.y; lidx = v + 1; }
        if (s.z > lmax) { lmax = s.z; lidx = v + 2; }
        if (s.w > lmax) { lmax = s.w; lidx = v + 3; }
    }

    s_red[tid] = lmax; s_redi[tid] = lidx;
    __syncthreads();
    for (int s = 128; s; s >>= 1) {
        if (tid < s) {
            float om = s_red[tid + s]; int oi = s_redi[tid + s];
            if (om > s_red[tid] || (om == s_red[tid] && oi < s_redi[tid])) {
                s_red[tid] = om; s_redi[tid] = oi;
            }
        }
        __syncthreads();
    }
    float M = s_red[0];
    int pos = s_redi[0];
    __syncthreads();

    float ps = 0.f;
#pragma unroll
    for (int i = 0; i < 20; i++) ps += expf(lv[i] - M);
    s_red[tid] = ps;
    __syncthreads();
    for (int s = 128; s; s >>= 1) {
        if (tid < s) s_red[tid] += s_red[tid + s];
        __syncthreads();
    }

    if (tid == 0) {
        float S = s_red[0];
        float val = -logf(S);            // = max(log_softmax)
        bool upd = (pos != 0);
        float sc = d_scores[b] + (upd ? val : 0.f);
        d_scores[b] = sc;
        out[b] = sc;                     // scores live at out[0..31]; last write wins
        int nt = upd ? pos : d_tok[b];
        d_tok[b] = nt;
        d_newtok[b] = nt;
        d_updf[b] = upd ? 1 : 0;
        out[kB + (size_t)b * kT + t] = (float)(upd ? pos : 0);
    }
}

// ---------------- Phase C1: gate partials  [x;h] @ [Wx;Wh] ----------------
__device__ void phaseC1(const float* __restrict__ embed, const float* __restrict__ Wx,
                        const float* __restrict__ Wh, float (*s_tile)[16]) {
    for (int tt = blockIdx.x; tt < TILES_C; tt += NBLK) {
        int hs  = tt & (HS_C - 1);
        int jch = (tt >> 5) % JCH_C;
        int bg  = tt / (HS_C * JCH_C);
        int hbase = hs * HCH_C;          // 0..1240 over concat dim 1280
        int j = jch * JW_C + threadIdx.x;

        for (int idx = threadIdx.x; idx < HCH_C * 16; idx += NTHR) {
            int hh = idx >> 4, bb = idx & 15;
            int gb = bg * 16 + bb;
            int i = hbase + hh;
            float xv = (i < kH) ? embed[(size_t)d_newtok[gb] * kH + i]
                                : d_h[gb * kH + (i - kH)];
            s_tile[hh][bb] = xv;
        }
        __syncthreads();

        float acc[16];
#pragma unroll
        for (int i = 0; i < 16; i++) acc[i] = 0.f;
        const float* wp = (hbase < kH ? Wx + (size_t)hbase * kG
                                      : Wh + (size_t)(hbase - kH) * kG) + j;
#pragma unroll 4
        for (int hh = 0; hh < HCH_C; ++hh) {
            float w = wp[0]; wp += kG;
#pragma unroll
            for (int bb = 0; bb < 16; ++bb) acc[bb] += s_tile[hh][bb] * w;
        }
        int gate = j / kH;
        int k = j - gate * kH;
#pragma unroll
        for (int bb = 0; bb < 16; ++bb)
            d_gpart[(((size_t)hs * kB + bg * 16 + bb) * kH + k) * 4 + gate] = acc[bb];
        __syncthreads();
    }
}

// ---------------- Phase C2: gate reduce + LSTM update + next joint ----------------
__device__ void phaseC2(int tnext, const float* __restrict__ tn, const float* __restrict__ bias) {
    int b = blockIdx.x;
    if (b >= kB) return;
    int upd = d_updf[b];
    for (int kk = 0; kk < 3; ++kk) {
        int k = threadIdx.x + 256 * kk;
        if (k >= kH) break;
        float cold = d_c[b * kH + k];
        float hnew, cnew;
        if (upd) {
            float4 acc;
            acc.x = bias[k]; acc.y = bias[kH + k];
            acc.z = bias[2 * kH + k]; acc.w = bias[3 * kH + k];
#pragma unroll 8
            for (int hs = 0; hs < HS_C; ++hs) {
                float4 p = *(const float4*)&d_gpart[(((size_t)hs * kB + b) * kH + k) * 4];
                acc.x += p.x; acc.y += p.y; acc.z += p.z; acc.w += p.w;
            }
            float si = 1.f / (1.f + expf(-acc.x));
            float sf = 1.f / (1.f + expf(-acc.y));
            float tg = tanhf(acc.z);
            float so = 1.f / (1.f + expf(-acc.w));
            float c2 = sf * cold + si * tg;
            float h2 = so * tanhf(c2);
            hnew = h2; cnew = c2;
            d_h[b * kH + k] = h2;
            d_c[b * kH + k] = c2;
        } else {
            hnew = d_h[b * kH + k];
            cnew = cold;
        }
        (void)cnew;
        // out_PN == h always (init sets them equal; both updated together)
        d_joint[b * kH + k] = tanhf(tn[((size_t)b * kT + tnext) * kH + k] + hnew);
    }
}

__global__ void __launch_bounds__(NTHR)
transducer_kernel(const float* __restrict__ tn, const float* __restrict__ embed,
                  const float* __restrict__ Wx, const float* __restrict__ Wh,
                  const float* __restrict__ bias, const float* __restrict__ Wc,
                  const float* __restrict__ bc, float* __restrict__ out) {
    __shared__ float s_tile[HCH_C][16];   // 40x16, shared by phases A and C1
    __shared__ float s_red[NTHR];
    __shared__ int   s_redi[NTHR];

    int gid = blockIdx.x * NTHR + threadIdx.x;

    // INIT: zero state (must re-run each graph replay)
    for (int i = gid; i < kB * kH; i += NBLK * NTHR) { d_h[i] = 0.f; d_c[i] = 0.f; }
    if (gid < kB) { d_scores[gid] = 0.f; d_tok[gid] = 0; d_newtok[gid] = 0; d_updf[gid] = 1; }
    grid_barrier();

    // Initial LSTM step: tok=BLANK, h0=c0=0 -> h,c ; joint for t=0
    phaseC1(embed, Wx, Wh, s_tile);
    grid_barrier();
    phaseC2(0, tn, bias);
    grid_barrier();

    for (int t = 0; t < kT; ++t) {
        phaseA(Wc, s_tile);
        grid_barrier();
        phaseB(t, bc, out, s_red, s_redi);
        grid_barrier();
        if (t + 1 < kT) {
            phaseC1(embed, Wx, Wh, s_tile);
            grid_barrier();
            phaseC2(t + 1, tn, bias);
            grid_barrier();
        }
    }
}

extern "C" void kernel_launch(void* const* d_in, const int* in_sizes, int n_in,
                              void* d_out, int out_size) {
    const float* tn    = (const float*)d_in[0];  // [32,1000,640]
    const float* embed = (const float*)d_in[1];  // [5000,640]
    const float* Wx    = (const float*)d_in[2];  // [640,2560]
    const float* Wh    = (const float*)d_in[3];  // [640,2560]
    const float* bias  = (const float*)d_in[4];  // [2560]
    const float* Wc    = (const float*)d_in[5];  // [640,5000]
    const float* bc    = (const float*)d_in[6];  // [5000]
    float* out = (float*)d_out;                  // [32 scores][32*1000 preds]
    (void)in_sizes; (void)n_in; (void)out_size;
    transducer_kernel<<<NBLK, NTHR>>>(tn, embed, Wx, Wh, bias, Wc, bc, out);
}

// round 2
// speedup vs baseline: 1.3669x; 1.3669x over previous
#include <cuda_runtime.h>

// Persistent single-kernel greedy transducer decode. B=32,T=1000,H=640,V=5000.
constexpr int kB = 32;
constexpr int kT = 1000;
constexpr int kH = 640;
constexpr int kV = 5000;
constexpr int kG = 2560;   // 4*H

constexpr int NBLK = 148;
constexpr int NTHR = 256;

// Phase A: 2 bg x 20 vchunks(256) x 16 hsplits(depth 40) = 640 tiles
constexpr int HS_A = 16;
constexpr int TILES_A = 640;
// Phase C1: 2 bg x 10 jchunks(256) x 32 hsplits(depth 40) = 640 tiles
constexpr int HS_C = 32;
constexpr int TILES_C = 640;
// Phase B1: 32 b x 4 v-chunks of 1250
constexpr int BCH = 4, BCW = 1250;

// Scratch (device globals; no allocation allowed)
__device__ __align__(16) float d_part[(size_t)HS_A * kB * kV];
__device__ __align__(16) float d_gpart[(size_t)HS_C * kB * kH * 4];
__device__ __align__(16) float d_joint[kB * kH];
__device__ __align__(16) float d_h[kB * kH];
__device__ __align__(16) float d_c[kB * kH];
__device__ float d_scores[kB];
__device__ int   d_tok[kB];
__device__ int   d_newtok[kB];
__device__ int   d_updf[kB];
__device__ float d_bmax[kB * BCH];
__device__ int   d_bidx[kB * BCH];
__device__ float d_bsum[kB * BCH];

// Barrier state: counter and generation on separate 128B lines.
__device__ __align__(128) unsigned g_count[32];
__device__ __align__(128) unsigned g_gen[32];

__device__ __forceinline__ unsigned ld_cg(const unsigned* p) {
    unsigned v;
    asm volatile("ld.global.cg.u32 %0, [%1];" : "=r"(v) : "l"(p));
    return v;
}

__device__ __forceinline__ void grid_barrier() {
    __syncthreads();
    if (threadIdx.x == 0) {
        __threadfence();
        unsigned my = ld_cg(&g_gen[0]);
        if (atomicAdd(&g_count[0], 1u) == (unsigned)(NBLK - 1)) {
            atomicExch(&g_count[0], 0u);
            __threadfence();
            atomicAdd(&g_gen[0], 1u);
        } else {
            while (ld_cg(&g_gen[0]) == my) { __nanosleep(40); }
        }
        __threadfence();
    }
    __syncthreads();
}

// ---- f32x2 packed helpers ----
__device__ __forceinline__ unsigned long long pack2(float w) {
    unsigned long long r;
    asm("mov.b64 %0, {%1, %1};" : "=l"(r) : "f"(w));
    return r;
}
__device__ __forceinline__ void ffma2(unsigned long long& a, unsigned long long s,
                                      unsigned long long w) {
    asm("fma.rn.f32x2 %0, %1, %2, %0;" : "+l"(a) : "l"(s), "l"(w));
}
__device__ __forceinline__ float2 unpack2(unsigned long long a) {
    float2 f;
    asm("mov.b64 {%0, %1}, %2;" : "=f"(f.x), "=f"(f.y) : "l"(a));
    return f;
}
__device__ __forceinline__ float sigf(float x) { return 1.f / (1.f + expf(-x)); }

// Core register-tiled dot: acc[8] (16 b-lanes packed) over 40 depth rows.
// sA: [40][16] smem tile. wp: column pointer, row stride ws.
__device__ __forceinline__ void dot40(unsigned long long acc[8],
                                      const float (*sA)[16],
                                      const float* __restrict__ wp, int ws) {
    float wb[8];
#pragma unroll
    for (int j = 0; j < 8; j++) wb[j] = wp[(size_t)j * ws];
#pragma unroll
    for (int g = 0; g < 5; ++g) {
        float wc8[8];
#pragma unroll
        for (int j = 0; j < 8; j++) wc8[j] = wb[j];
        if (g < 4) {
            wp += (size_t)8 * ws;
#pragma unroll
            for (int j = 0; j < 8; j++) wb[j] = wp[(size_t)j * ws];
        }
#pragma unroll
        for (int j = 0; j < 8; j++) {
            int hh = g * 8 + j;
            unsigned long long w2 = pack2(wc8[j]);
            const double2* sp = reinterpret_cast<const double2*>(sA[hh]);
            double2 q0 = sp[0], q1 = sp[1], q2 = sp[2], q3 = sp[3];
            ffma2(acc[0], __double_as_longlong(q0.x), w2);
            ffma2(acc[1], __double_as_longlong(q0.y), w2);
            ffma2(acc[2], __double_as_longlong(q1.x), w2);
            ffma2(acc[3], __double_as_longlong(q1.y), w2);
            ffma2(acc[4], __double_as_longlong(q2.x), w2);
            ffma2(acc[5], __double_as_longlong(q2.y), w2);
            ffma2(acc[6], __double_as_longlong(q3.x), w2);
            ffma2(acc[7], __double_as_longlong(q3.y), w2);
        }
    }
}

// ---------------- Phase A: partial logits ----------------
__device__ void phaseA(const float* __restrict__ Wc, float (*sA)[16]) {
    for (int tt = blockIdx.x; tt < TILES_A; tt += NBLK) {
        int hs = tt & 15;
        int vch = (tt >> 4) % 20;
        int bg = tt / 320;
        int hbase = hs * 40;
        int v = vch * 256 + threadIdx.x;

        for (int idx = threadIdx.x; idx < 640; idx += NTHR) {
            int hh = idx >> 4, bb = idx & 15;
            sA[hh][bb] = d_joint[(bg * 16 + bb) * kH + hbase + hh];
        }
        __syncthreads();

        if (v < kV) {
            unsigned long long acc[8];
#pragma unroll
            for (int i = 0; i < 8; i++) acc[i] = 0ull;
            dot40(acc, sA, Wc + (size_t)hbase * kV + v, kV);
            size_t rb = (size_t)(hs * kB + bg * 16) * kV + v;
#pragma unroll
            for (int i = 0; i < 8; i++) {
                float2 f = unpack2(acc[i]);
                d_part[rb + (size_t)(2 * i) * kV] = f.x;
                d_part[rb + (size_t)(2 * i + 1) * kV] = f.y;
            }
        }
        __syncthreads();
    }
}

// ---------------- Phase B1: per (b,chunk) partial argmax + sumexp ----------------
__device__ void phaseB1(const float* __restrict__ bc, float* s_f, int* s_i, float* s_s) {
    int u = blockIdx.x;
    if (u >= kB * BCH) return;
    int b = u >> 2, ch = u & 3;
    int v0 = ch * BCW;
    int tid = threadIdx.x;

    float m = -1e30f;
    int mi = 0x7fffffff;
    float se = 0.f;
    for (int i = tid; i < BCW; i += NTHR) {
        int v = v0 + i;
        float s = bc[v];
#pragma unroll
        for (int hs = 0; hs < HS_A; hs++) s += d_part[((size_t)(hs * kB + b)) * kV + v];
        se += expf(s);
        if (s > m) { m = s; mi = v; }
    }
    s_f[tid] = m; s_i[tid] = mi; s_s[tid] = se;
    __syncthreads();
    for (int w = 128; w; w >>= 1) {
        if (tid < w) {
            float om = s_f[tid + w]; int oi = s_i[tid + w];
            if (om > s_f[tid] || (om == s_f[tid] && oi < s_i[tid])) { s_f[tid] = om; s_i[tid] = oi; }
            s_s[tid] += s_s[tid + w];
        }
        __syncthreads();
    }
    if (tid == 0) { d_bmax[u] = s_f[0]; d_bidx[u] = s_i[0]; d_bsum[u] = s_s[0]; }
}

// ---------------- Phase C1: gate partials [x;h] @ [Wx;Wh] ----------------
__device__ void phaseC1(const float* __restrict__ embed, const float* __restrict__ Wx,
                        const float* __restrict__ Wh, float (*sA)[16], int* s_ntk,
                        bool comb) {
    for (int tt = blockIdx.x; tt < TILES_C; tt += NBLK) {
        int hs = tt & 31;
        int jch = (tt >> 5) % 10;
        int bg = tt / 320;
        int hbase = hs * 40;                    // over concat dim 1280
        int j = jch * 256 + threadIdx.x;

        if (threadIdx.x < 16) {
            int b = bg * 16 + threadIdx.x;
            int nt;
            if (comb) {
                float m = -1e30f; int mi = 0;
#pragma unroll
                for (int ch = 0; ch < BCH; ch++) {
                    float cm = d_bmax[b * BCH + ch];
                    int ci = d_bidx[b * BCH + ch];
                    if (cm > m) { m = cm; mi = ci; }
                }
                int upd = (mi != 0);
                nt = upd ? mi : d_tok[b];
                d_updf[b] = upd;
                d_newtok[b] = nt;
            } else {
                nt = d_newtok[b];
            }
            s_ntk[threadIdx.x] = nt;
        }
        __syncthreads();

        for (int idx = threadIdx.x; idx < 640; idx += NTHR) {
            int hh = idx >> 4, bb = idx & 15;
            int i = hbase + hh;
            int gb = bg * 16 + bb;
            sA[hh][bb] = (i < kH) ? embed[(size_t)s_ntk[bb] * kH + i]
                                  : d_h[gb * kH + (i - kH)];
        }
        __syncthreads();

        {
            unsigned long long acc[8];
#pragma unroll
            for (int i = 0; i < 8; i++) acc[i] = 0ull;
            const float* wbase = (hbase < kH) ? (Wx + (size_t)hbase * kG)
                                              : (Wh + (size_t)(hbase - kH) * kG);
            dot40(acc, sA, wbase + j, kG);
            int gate = j / kH;
            int k = j - gate * kH;
#pragma unroll
            for (int i = 0; i < 8; i++) {
                float2 f = unpack2(acc[i]);
                int bb0 = 2 * i;
                d_gpart[(((size_t)hs * kB + bg * 16 + bb0) * kH + k) * 4 + gate] = f.x;
                d_gpart[(((size_t)hs * kB + bg * 16 + bb0 + 1) * kH + k) * 4 + gate] = f.y;
            }
        }
        __syncthreads();
    }
}

// ---------------- Phase C2: gate reduce + LSTM + next joint + emit ----------------
__device__ void phaseC2(int t, const float* __restrict__ tn, const float* __restrict__ bias,
                        float* __restrict__ out) {
    int gid = blockIdx.x * NTHR + threadIdx.x;
    if (gid >= kB * kH) return;
    int b = gid / kH;
    int k = gid - b * kH;

    if (t < kT - 1) {  // includes init t=-1; at t=999 state is dead
        int upd = d_updf[b];
        float hnew;
        if (upd) {
            float4 acc;
            acc.x = bias[k]; acc.y = bias[kH + k];
            acc.z = bias[2 * kH + k]; acc.w = bias[3 * kH + k];
#pragma unroll 8
            for (int hs = 0; hs < HS_C; hs++) {
                float4 p = *(const float4*)&d_gpart[(((size_t)hs * kB + b) * kH + k) * 4];
                acc.x += p.x; acc.y += p.y; acc.z += p.z; acc.w += p.w;
            }
            float si = sigf(acc.x), sf = sigf(acc.y);
            float tg = tanhf(acc.z), so = sigf(acc.w);
            float c2 = sf * d_c[gid] + si * tg;
            float h2 = so * tanhf(c2);
            d_c[gid] = c2; d_h[gid] = h2;
            hnew = h2;
        } else {
            hnew = d_h[gid];
        }
        d_joint[gid] = tanhf(tn[((size_t)b * kT + (t + 1)) * kH + k] + hnew);
    }

    if (k == 0 && t >= 0) {
        float m = -1e30f; int mi = 0; float S = 0.f;
#pragma unroll
        for (int ch = 0; ch < BCH; ch++) {
            float cm = d_bmax[b * BCH + ch];
            int ci = d_bidx[b * BCH + ch];
            S += d_bsum[b * BCH + ch];
            if (cm > m) { m = cm; mi = ci; }
        }
        int upd = (mi != 0);
        float val = m - logf(S);
        float sc = d_scores[b] + (upd ? val : 0.f);
        d_scores[b] = sc;
        if (t == kT - 1) out[b] = sc;
        out[kB + (size_t)b * kT + t] = (float)(upd ? mi : 0);
        if (upd) d_tok[b] = mi;
    }
}

__global__ void __launch_bounds__(NTHR)
transducer_kernel(const float* __restrict__ tn, const float* __restrict__ embed,
                  const float* __restrict__ Wx, const float* __restrict__ Wh,
                  const float* __restrict__ bias, const float* __restrict__ Wc,
                  const float* __restrict__ bc, float* __restrict__ out) {
    __shared__ __align__(16) float sA[40][16];
    __shared__ int s_ntk[16];
    __shared__ float s_f[NTHR];
    __shared__ int   s_i[NTHR];
    __shared__ float s_s[NTHR];

    int gid = blockIdx.x * NTHR + threadIdx.x;

    // INIT (re-runs each graph replay)
    for (int i = gid; i < kB * kH; i += NBLK * NTHR) { d_h[i] = 0.f; d_c[i] = 0.f; }
    if (gid < kB) { d_scores[gid] = 0.f; d_tok[gid] = 0; d_newtok[gid] = 0; d_updf[gid] = 1; }
    grid_barrier();

    // Initial LSTM step (tok=0, zero state) -> h, joint(0)
    phaseC1(embed, Wx, Wh, sA, s_ntk, false);
    grid_barrier();
    phaseC2(-1, tn, bias, out);
    grid_barrier();

    for (int t = 0; t < kT; ++t) {
        phaseA(Wc, sA);
        grid_barrier();
        phaseB1(bc, s_f, s_i, s_s);
        grid_barrier();
        if (t < kT - 1) {
            phaseC1(embed, Wx, Wh, sA, s_ntk, true);
            grid_barrier();
        }
        phaseC2(t, tn, bias, out);
        grid_barrier();
    }
}

extern "C" void kernel_launch(void* const* d_in, const int* in_sizes, int n_in,
                              void* d_out, int out_size) {
    const float* tn    = (const float*)d_in[0];
    const float* embed = (const float*)d_in[1];
    const float* Wx    = (const float*)d_in[2];
    const float* Wh    = (const float*)d_in[3];
    const float* bias  = (const float*)d_in[4];
    const float* Wc    = (const float*)d_in[5];
    const float* bc    = (const float*)d_in[6];
    float* out = (float*)d_out;
    (void)in_sizes; (void)n_in; (void)out_size;
    transducer_kernel<<<NBLK, NTHR>>>(tn, embed, Wx, Wh, bias, Wc, bc, out);
}

// round 3
// speedup vs baseline: 1.5917x; 1.1644x over previous
#include <cuda_runtime.h>

// Persistent single-kernel greedy transducer decode. B=32,T=1000,H=640,V=5000.
// Round 3: 4 blocks/SM, precomputed embed@Wx, fused A+Ch GEMM phase, 3 barriers/step.

typedef unsigned long long ull;

constexpr int kB = 32;
constexpr int kT = 1000;
constexpr int kH = 640;
constexpr int kV = 5000;
constexpr int kG = 2560;   // 4*H

constexpr int NBLK = 592;  // 4 blocks per SM (148 SMs)
constexpr int NTHR = 256;

constexpr int HS = 16;               // depth splits of 40 over 640
constexpr int TILES_A = 640;         // 2bg x 20vch(256) x 16hs
constexpr int TILES_CH = 320;        // 2bg x 10jch(256) x 16hs
constexpr int POOL = TILES_A + TILES_CH;
constexpr int BCH = 16, BCW = 313;   // phase-B: 16 v-chunks x 32 rows = 512 units
constexpr int PTILES = 313 * 10;     // precompute: 313 row-blocks(16) x 10 jch

// ---- device globals (no allocation allowed) ----
__device__ __align__(16) float d_xwx[(size_t)kV * kH * 4];   // [v][k][gate] 51.2MB
__device__ __align__(16) float d_part[(size_t)HS * kB * kV]; // 10.2MB
__device__ __align__(16) float d_gpart[(size_t)HS * kB * kH * 4]; // 5.2MB
__device__ __align__(16) float d_joint[kB * kH];
__device__ __align__(16) float d_h[kB * kH];
__device__ __align__(16) float d_c[kB * kH];
__device__ float d_scores[kB];
__device__ int   d_tok[kB];
__device__ float d_bmax[kB * BCH];
__device__ int   d_bidx[kB * BCH];
__device__ float d_bsum[kB * BCH];
__device__ __align__(128) unsigned g_count[32];
__device__ __align__(128) unsigned g_gen[32];

__device__ __forceinline__ unsigned ld_cg(const unsigned* p) {
    unsigned v;
    asm volatile("ld.global.cg.u32 %0, [%1];" : "=r"(v) : "l"(p));
    return v;
}

__device__ __forceinline__ void grid_barrier() {
    __syncthreads();
    if (threadIdx.x == 0) {
        __threadfence();
        unsigned my = ld_cg(&g_gen[0]);
        if (atomicAdd(&g_count[0], 1u) == (unsigned)(NBLK - 1)) {
            atomicExch(&g_count[0], 0u);
            __threadfence();
            atomicAdd(&g_gen[0], 1u);
        } else {
            while (ld_cg(&g_gen[0]) == my) { __nanosleep(40); }
        }
        __threadfence();
    }
    __syncthreads();
}

// ---- f32x2 packed helpers ----
__device__ __forceinline__ ull pack2(float w) {
    ull r;
    asm("mov.b64 %0, {%1, %1};" : "=l"(r) : "f"(w));
    return r;
}
__device__ __forceinline__ void ffma2(ull& a, ull s, ull w) {
    asm("fma.rn.f32x2 %0, %1, %2, %0;" : "+l"(a) : "l"(s), "l"(w));
}
__device__ __forceinline__ float2 unpack2(ull a) {
    float2 f;
    asm("mov.b64 {%0, %1}, %2;" : "=f"(f.x), "=f"(f.y) : "l"(a));
    return f;
}
__device__ __forceinline__ float sigf(float x) { return 1.f / (1.f + expf(-x)); }

// Register-tiled dot over 40 depth rows, 16 b-lanes packed in 8 f32x2 accs.
// sA rows padded to 20 floats (80B, 16B-aligned). 4-deep weight prefetch.
__device__ __forceinline__ void dot40(ull acc[8], const float (*sA)[20],
                                      const float* __restrict__ wp, size_t ws) {
    float wb[4];
#pragma unroll
    for (int j = 0; j < 4; j++) wb[j] = wp[j * ws];
#pragma unroll
    for (int g = 0; g < 10; ++g) {
        float wc[4];
#pragma unroll
        for (int j = 0; j < 4; j++) wc[j] = wb[j];
        if (g < 9) {
            wp += 4 * ws;
#pragma unroll
            for (int j = 0; j < 4; j++) wb[j] = wp[j * ws];
        }
#pragma unroll
        for (int j = 0; j < 4; j++) {
            int hh = g * 4 + j;
            ull w2 = pack2(wc[j]);
            const double2* sp = reinterpret_cast<const double2*>(sA[hh]);
            double2 q0 = sp[0], q1 = sp[1], q2 = sp[2], q3 = sp[3];
            ffma2(acc[0], __double_as_longlong(q0.x), w2);
            ffma2(acc[1], __double_as_longlong(q0.y), w2);
            ffma2(acc[2], __double_as_longlong(q1.x), w2);
            ffma2(acc[3], __double_as_longlong(q1.y), w2);
            ffma2(acc[4], __double_as_longlong(q2.x), w2);
            ffma2(acc[5], __double_as_longlong(q2.y), w2);
            ffma2(acc[6], __double_as_longlong(q3.x), w2);
            ffma2(acc[7], __double_as_longlong(q3.y), w2);
        }
    }
}

// Fill a [40 depth][16 b] activation tile from a row-major [rows][640] source.
__device__ __forceinline__ void fill_act(float (*dst)[20], const float* __restrict__ src,
                                         int row0, int hbase) {
    for (int idx = threadIdx.x; idx < 640; idx += NTHR) {
        int hh = idx >> 4, bb = idx & 15;
        dst[hh][bb] = src[(row0 + bb) * kH + hbase + hh];
    }
}
__device__ __forceinline__ void fill_embed(float (*dst)[20], const float* __restrict__ embed,
                                           int v0, int hbase) {
    for (int idx = threadIdx.x; idx < 640; idx += NTHR) {
        int hh = idx >> 4, bb = idx & 15;
        int v = v0 + bb;
        dst[hh][bb] = (v < kV) ? embed[(size_t)v * kH + hbase + hh] : 0.f;
    }
}

// ---- fused GEMM phase: A-tiles (joint@Wc) + Ch-tiles (h@Wh) ----
__device__ __forceinline__ void gemm_fill(int tt, float (*buf)[20]) {
    if (tt < TILES_A) {
        int hs = tt & 15, bg = tt / 320;
        fill_act(buf, d_joint, bg * 16, hs * 40);
    } else {
        int u = tt - TILES_A;
        int hs = u & 15, bg = u / 160;
        fill_act(buf, d_h, bg * 16, hs * 40);
    }
}

__device__ __forceinline__ void gemm_compute(int tt, const float (*buf)[20],
                                             const float* __restrict__ Wc,
                                             const float* __restrict__ Wh) {
    if (tt < TILES_A) {
        int hs = tt & 15, vch = (tt >> 4) % 20, bg = tt / 320;
        int v = vch * 256 + threadIdx.x;
        if (v < kV) {
            ull acc[8] = {0, 0, 0, 0, 0, 0, 0, 0};
            dot40(acc, buf, Wc + (size_t)(hs * 40) * kV + v, kV);
            size_t rb = (size_t)(hs * kB + bg * 16) * kV + v;
#pragma unroll
            for (int i = 0; i < 8; i++) {
                float2 f = unpack2(acc[i]);
                d_part[rb + (size_t)(2 * i) * kV] = f.x;
                d_part[rb + (size_t)(2 * i + 1) * kV] = f.y;
            }
        }
    } else {
        int u = tt - TILES_A;
        int hs = u & 15, jch = (u >> 4) % 10, bg = u / 160;
        int j = jch * 256 + threadIdx.x;
        ull acc[8] = {0, 0, 0, 0, 0, 0, 0, 0};
        dot40(acc, buf, Wh + (size_t)(hs * 40) * kG + j, kG);
        int gate = j / kH, k = j - gate * kH;
#pragma unroll
        for (int i = 0; i < 8; i++) {
            float2 f = unpack2(acc[i]);
            d_gpart[(((size_t)hs * kB + bg * 16 + 2 * i) * kH + k) * 4 + gate] = f.x;
            d_gpart[(((size_t)hs * kB + bg * 16 + 2 * i + 1) * kH + k) * 4 + gate] = f.y;
        }
    }
}

// ---- phase B: per (b, v-chunk) partial argmax + sumexp ----
__device__ void phaseB(const float* __restrict__ bc, float* s_f, int* s_i, float* s_s) {
    int u = blockIdx.x;
    if (u >= kB * BCH) return;
    int b = u >> 4, ch = u & 15;
    int v0 = ch * BCW;
    int v1 = v0 + BCW; if (v1 > kV) v1 = kV;
    int tid = threadIdx.x;

    float m = -1e30f;
    int mi = 0x7fffffff;
    float se = 0.f;
    for (int v = v0 + tid; v < v1; v += NTHR) {
        float s = bc[v];
#pragma unroll
        for (int hs = 0; hs < HS; hs++) s += d_part[((size_t)(hs * kB + b)) * kV + v];
        se += expf(s);
        if (s > m) { m = s; mi = v; }
    }
    s_f[tid] = m; s_i[tid] = mi; s_s[tid] = se;
    __syncthreads();
    for (int w = 128; w; w >>= 1) {
        if (tid < w) {
            float om = s_f[tid + w]; int oi = s_i[tid + w];
            if (om > s_f[tid] || (om == s_f[tid] && oi < s_i[tid])) { s_f[tid] = om; s_i[tid] = oi; }
            s_s[tid] += s_s[tid + w];
        }
        __syncthreads();
    }
    if (tid == 0) { d_bmax[u] = s_f[0]; d_bidx[u] = s_i[0]; d_bsum[u] = s_s[0]; }
}

// ---- phase C2: combine + LSTM update (xWx lookup + Wh partial reduce) + next joint ----
__device__ void phaseC2(int t, const float* __restrict__ tn, const float* __restrict__ bias,
                        float* __restrict__ out) {
    int gid = blockIdx.x * NTHR + threadIdx.x;
    if (gid >= kB * kH) return;
    int b = gid / kH, k = gid - b * kH;

    float m = -1e30f; int mi = 0;
#pragma unroll
    for (int ch = 0; ch < BCH; ch++) {
        float cm = d_bmax[b * BCH + ch];
        int ci = d_bidx[b * BCH + ch];
        if (cm > m) { m = cm; mi = ci; }
    }
    int upd = (mi != 0);
    int nt = upd ? mi : d_tok[b];   // race-safe: writer stores the same value readers compute

    if (t < kT - 1) {
        float hnew;
        if (upd) {
            float4 a = *(const float4*)&d_xwx[((size_t)nt * kH + k) * 4];
            a.x += bias[k]; a.y += bias[kH + k]; a.z += bias[2 * kH + k]; a.w += bias[3 * kH + k];
#pragma unroll
            for (int hs = 0; hs < HS; hs++) {
                float4 p = *(const float4*)&d_gpart[(((size_t)hs * kB + b) * kH + k) * 4];
                a.x += p.x; a.y += p.y; a.z += p.z; a.w += p.w;
            }
            float c2 = sigf(a.y) * d_c[gid] + sigf(a.x) * tanhf(a.z);
            float h2 = sigf(a.w) * tanhf(c2);
            d_c[gid] = c2; d_h[gid] = h2;
            hnew = h2;
        } else {
            hnew = d_h[gid];
        }
        d_joint[gid] = tanhf(tn[((size_t)b * kT + (t + 1)) * kH + k] + hnew);
    }

    if (k == 0) {
        float S = 0.f;
#pragma unroll
        for (int ch = 0; ch < BCH; ch++) S += d_bsum[b * BCH + ch];
        float val = m - logf(S);
        float sc = d_scores[b] + (upd ? val : 0.f);
        d_scores[b] = sc;
        if (t == kT - 1) out[b] = sc;
        out[kB + (size_t)b * kT + t] = (float)(upd ? mi : 0);
        if (upd) d_tok[b] = mi;
    }
}

// ---- one-time per launch: xWx = embed @ Wx  -> [v][k][gate] ----
__device__ void precompute_xwx(const float* __restrict__ embed, const float* __restrict__ Wx,
                               float (*sA)[20]) {
    for (int tp = blockIdx.x; tp < PTILES; tp += NBLK) {
        int rb = tp / 10, jch = tp % 10;
        int v0 = rb * 16;
        int j = jch * 256 + threadIdx.x;
        ull acc[8] = {0, 0, 0, 0, 0, 0, 0, 0};
        for (int hs = 0; hs < 16; hs++) {
            __syncthreads();
            fill_embed(sA, embed, v0, hs * 40);
            __syncthreads();
            dot40(acc, sA, Wx + (size_t)(hs * 40) * kG + j, kG);
        }
        int gate = j / kH, k = j - gate * kH;
#pragma unroll
        for (int i = 0; i < 8; i++) {
            float2 f = unpack2(acc[i]);
            int v = v0 + 2 * i;
            if (v < kV)     d_xwx[((size_t)v * kH + k) * 4 + gate] = f.x;
            if (v + 1 < kV) d_xwx[((size_t)(v + 1) * kH + k) * 4 + gate] = f.y;
        }
    }
}

// ---- init step: tok=0, h0=c0=0 -> h1,c1, joint(0) ----
__device__ void initC2(const float* __restrict__ tn, const float* __restrict__ bias) {
    int gid = blockIdx.x * NTHR + threadIdx.x;
    if (gid >= kB * kH) return;
    int b = gid / kH, k = gid - b * kH;
    float4 a = *(const float4*)&d_xwx[(size_t)k * 4];   // token 0
    a.x += bias[k]; a.y += bias[kH + k]; a.z += bias[2 * kH + k]; a.w += bias[3 * kH + k];
    float c1 = sigf(a.x) * tanhf(a.z);                  // f-gate * 0 dropped
    float h1 = sigf(a.w) * tanhf(c1);
    d_c[gid] = c1; d_h[gid] = h1;
    d_joint[gid] = tanhf(tn[(size_t)b * kT * kH + k] + h1);
    if (k == 0) { d_scores[b] = 0.f; d_tok[b] = 0; }
}

__global__ void __launch_bounds__(NTHR, 4)
transducer_kernel(const float* __restrict__ tn, const float* __restrict__ embed,
                  const float* __restrict__ Wx, const float* __restrict__ Wh,
                  const float* __restrict__ bias, const float* __restrict__ Wc,
                  const float* __restrict__ bc, float* __restrict__ out) {
    __shared__ __align__(16) float sA[2][40][20];
    __shared__ float s_f[NTHR];
    __shared__ int   s_i[NTHR];
    __shared__ float s_s[NTHR];

    precompute_xwx(embed, Wx, sA[0]);
    grid_barrier();
    initC2(tn, bias);
    grid_barrier();

    for (int t = 0; t < kT; ++t) {
        int pool = (t < kT - 1) ? POOL : TILES_A;   // last step: state is dead, skip Ch

        // fused GEMM phase, double-buffered smem tiles (one sync per tile)
        {
            int tt = blockIdx.x;
            int p = 0;
            if (tt < pool) gemm_fill(tt, sA[0]);
            for (; tt < pool; tt += NBLK) {
                __syncthreads();
                int nx = tt + NBLK;
                if (nx < pool) gemm_fill(nx, sA[p ^ 1]);
                gemm_compute(tt, sA[p], Wc, Wh);
                p ^= 1;
            }
        }
        grid_barrier();
        phaseB(bc, s_f, s_i, s_s);
        grid_barrier();
        phaseC2(t, tn, bias, out);
        grid_barrier();
    }
}

extern "C" void kernel_launch(void* const* d_in, const int* in_sizes, int n_in,
                              void* d_out, int out_size) {
    const float* tn    = (const float*)d_in[0];
    const float* embed = (const float*)d_in[1];
    const float* Wx    = (const float*)d_in[2];
    const float* Wh    = (const float*)d_in[3];
    const float* bias  = (const float*)d_in[4];
    const float* Wc    = (const float*)d_in[5];
    const float* bc    = (const float*)d_in[6];
    float* out = (float*)d_out;
    (void)in_sizes; (void)n_in; (void)out_size;
    transducer_kernel<<<NBLK, NTHR>>>(tn, embed, Wx, Wh, bias, Wc, bc, out);
}

// round 4
// speedup vs baseline: 2.5176x; 1.5817x over previous
#include <cuda_runtime.h>

// Persistent single-kernel greedy transducer decode. B=32,T=1000,H=640,V=5000.
// Round 4: depth-80 tiles (1 tile/block), transposed activations for coalesced fills.

typedef unsigned long long ull;

constexpr int kB = 32;
constexpr int kT = 1000;
constexpr int kH = 640;
constexpr int kV = 5000;
constexpr int kG = 2560;   // 4*H

constexpr int NBLK = 592;  // 4 blocks/SM x 148 SMs (co-resident)
constexpr int NTHR = 256;

constexpr int HS = 8;                // depth splits of 80 over 640
constexpr int DEP = 80;
constexpr int TILES_A = 320;         // 20vch(256) x 8hs x 2bg
constexpr int TILES_CH = 160;        // 10jch(256) x 8hs x 2bg
constexpr int POOL = TILES_A + TILES_CH;   // 480
constexpr int BCH = 16, BCW = 313;   // phase-B: 16 v-chunks x 32 rows
constexpr int PTILES = 313 * 10;     // precompute tiles

// ---- device globals ----
__device__ __align__(16) float d_xwx[(size_t)kV * kH * 4];        // [v][k][gate] 51.2MB
__device__ __align__(16) float d_part[(size_t)HS * kB * kV];      // 5.12MB
__device__ __align__(16) float d_gpart[(size_t)HS * kB * kH * 4]; // 2.62MB
__device__ __align__(16) float d_jointT[kH * kB];                 // [k][b]
__device__ __align__(16) float d_hT[kH * kB];                     // [k][b]
__device__ __align__(16) float d_c[kB * kH];                      // [b][k]
__device__ float d_scores[kB];
__device__ int   d_tok[kB];
__device__ float d_bmax[kB * BCH];
__device__ int   d_bidx[kB * BCH];
__device__ float d_bsum[kB * BCH];
__device__ __align__(128) unsigned g_count[32];
__device__ __align__(128) unsigned g_gen[32];

__device__ __forceinline__ unsigned ld_cg(const unsigned* p) {
    unsigned v;
    asm volatile("ld.global.cg.u32 %0, [%1];" : "=r"(v) : "l"(p));
    return v;
}

__device__ __forceinline__ void grid_barrier() {
    __syncthreads();
    if (threadIdx.x == 0) {
        __threadfence();
        unsigned my = ld_cg(&g_gen[0]);
        if (atomicAdd(&g_count[0], 1u) == (unsigned)(NBLK - 1)) {
            atomicExch(&g_count[0], 0u);
            __threadfence();
            atomicAdd(&g_gen[0], 1u);
        } else {
            while (ld_cg(&g_gen[0]) == my) { __nanosleep(40); }
        }
        __threadfence();
    }
    __syncthreads();
}

// ---- f32x2 packed helpers ----
__device__ __forceinline__ ull pack2(float w) {
    ull r;
    asm("mov.b64 %0, {%1, %1};" : "=l"(r) : "f"(w));
    return r;
}
__device__ __forceinline__ void ffma2(ull& a, ull s, ull w) {
    asm("fma.rn.f32x2 %0, %1, %2, %0;" : "+l"(a) : "l"(s), "l"(w));
}
__device__ __forceinline__ float2 unpack2(ull a) {
    float2 f;
    asm("mov.b64 {%0, %1}, %2;" : "=f"(f.x), "=f"(f.y) : "l"(a));
    return f;
}
__device__ __forceinline__ float sigf(float x) { return 1.f / (1.f + expf(-x)); }

// Register-tiled dot over 80 depth rows, 16 b-lanes in 8 f32x2 accumulators.
// sA rows padded to 20 floats (80B). 4-row weight prefetch pipeline.
__device__ __forceinline__ void dot80(ull acc[8], const float (*sA)[20],
                                      const float* __restrict__ wp, size_t ws) {
    float wb[4];
#pragma unroll
    for (int j = 0; j < 4; j++) wb[j] = wp[j * ws];
#pragma unroll
    for (int g = 0; g < 20; ++g) {
        float wc[4];
#pragma unroll
        for (int j = 0; j < 4; j++) wc[j] = wb[j];
        if (g < 19) {
            wp += 4 * ws;
#pragma unroll
            for (int j = 0; j < 4; j++) wb[j] = wp[j * ws];
        }
#pragma unroll
        for (int j = 0; j < 4; j++) {
            int hh = g * 4 + j;
            ull w2 = pack2(wc[j]);
            const double2* sp = reinterpret_cast<const double2*>(sA[hh]);
            double2 q0 = sp[0], q1 = sp[1], q2 = sp[2], q3 = sp[3];
            ffma2(acc[0], __double_as_longlong(q0.x), w2);
            ffma2(acc[1], __double_as_longlong(q0.y), w2);
            ffma2(acc[2], __double_as_longlong(q1.x), w2);
            ffma2(acc[3], __double_as_longlong(q1.y), w2);
            ffma2(acc[4], __double_as_longlong(q2.x), w2);
            ffma2(acc[5], __double_as_longlong(q2.y), w2);
            ffma2(acc[6], __double_as_longlong(q3.x), w2);
            ffma2(acc[7], __double_as_longlong(q3.y), w2);
        }
    }
}

// Coalesced tile fill from transposed [k][b] source.
__device__ __forceinline__ void fill_T(float (*dst)[20], const float* __restrict__ srcT,
                                       int bg, int hbase) {
    for (int idx = threadIdx.x; idx < DEP * 16; idx += NTHR) {
        int hh = idx >> 4, bb = idx & 15;
        dst[hh][bb] = srcT[(hbase + hh) * kB + bg * 16 + bb];
    }
}
__device__ __forceinline__ void fill_embed(float (*dst)[20], const float* __restrict__ embed,
                                           int v0, int hbase) {
    for (int idx = threadIdx.x; idx < DEP * 16; idx += NTHR) {
        int hh = idx >> 4, bb = idx & 15;
        int v = v0 + bb;
        dst[hh][bb] = (v < kV) ? embed[(size_t)v * kH + hbase + hh] : 0.f;
    }
}

// ---- fused GEMM phase: A tiles (jointT@Wc) + Ch tiles (hT@Wh) ----
__device__ __forceinline__ void gemm_tile(int tt, float (*sA)[20],
                                          const float* __restrict__ Wc,
                                          const float* __restrict__ Wh) {
    if (tt < TILES_A) {
        int hs = tt & 7, vch = (tt >> 3) % 20, bg = tt / 160;
        int hbase = hs * DEP;
        fill_T(sA, d_jointT, bg, hbase);
        __syncthreads();
        int v = vch * 256 + threadIdx.x;
        if (v < kV) {
            ull acc[8] = {0, 0, 0, 0, 0, 0, 0, 0};
            dot80(acc, sA, Wc + (size_t)hbase * kV + v, kV);
            size_t rb = (size_t)(hs * kB + bg * 16) * kV + v;
#pragma unroll
            for (int i = 0; i < 8; i++) {
                float2 f = unpack2(acc[i]);
                d_part[rb + (size_t)(2 * i) * kV] = f.x;
                d_part[rb + (size_t)(2 * i + 1) * kV] = f.y;
            }
        }
    } else {
        int u = tt - TILES_A;
        int hs = u & 7, jch = (u >> 3) % 10, bg = u / 80;
        int hbase = hs * DEP;
        fill_T(sA, d_hT, bg, hbase);
        __syncthreads();
        int j = jch * 256 + threadIdx.x;
        ull acc[8] = {0, 0, 0, 0, 0, 0, 0, 0};
        dot80(acc, sA, Wh + (size_t)hbase * kG + j, kG);
        int gate = j / kH, k = j - gate * kH;
#pragma unroll
        for (int i = 0; i < 8; i++) {
            float2 f = unpack2(acc[i]);
            d_gpart[(((size_t)hs * kB + bg * 16 + 2 * i) * kH + k) * 4 + gate] = f.x;
            d_gpart[(((size_t)hs * kB + bg * 16 + 2 * i + 1) * kH + k) * 4 + gate] = f.y;
        }
    }
}

// ---- phase B: per (b, v-chunk) partial argmax + sumexp ----
__device__ void phaseB(const float* __restrict__ bc, float* s_f, int* s_i, float* s_s) {
    int u = blockIdx.x;
    if (u >= kB * BCH) return;
    int b = u >> 4, ch = u & 15;
    int v0 = ch * BCW;
    int v1 = v0 + BCW; if (v1 > kV) v1 = kV;
    int tid = threadIdx.x;

    float m = -1e30f;
    int mi = 0x7fffffff;
    float se = 0.f;
    for (int v = v0 + tid; v < v1; v += NTHR) {
        float s = bc[v];
#pragma unroll
        for (int hs = 0; hs < HS; hs++) s += d_part[((size_t)(hs * kB + b)) * kV + v];
        se += expf(s);
        if (s > m) { m = s; mi = v; }
    }
    s_f[tid] = m; s_i[tid] = mi; s_s[tid] = se;
    __syncthreads();
    for (int w = 128; w; w >>= 1) {
        if (tid < w) {
            float om = s_f[tid + w]; int oi = s_i[tid + w];
            if (om > s_f[tid] || (om == s_f[tid] && oi < s_i[tid])) { s_f[tid] = om; s_i[tid] = oi; }
            s_s[tid] += s_s[tid + w];
        }
        __syncthreads();
    }
    if (tid == 0) { d_bmax[u] = s_f[0]; d_bidx[u] = s_i[0]; d_bsum[u] = s_s[0]; }
}

// ---- phase C2: combine + LSTM update + next joint + emit ----
__device__ void phaseC2(int t, const float* __restrict__ tn, const float* __restrict__ bias,
                        float* __restrict__ out) {
    int gid = blockIdx.x * NTHR + threadIdx.x;
    if (gid >= kB * kH) return;
    int b = gid / kH, k = gid - b * kH;

    float m = -1e30f; int mi = 0;
#pragma unroll
    for (int ch = 0; ch < BCH; ch++) {
        float cm = d_bmax[b * BCH + ch];
        int ci = d_bidx[b * BCH + ch];
        if (cm > m) { m = cm; mi = ci; }
    }
    int upd = (mi != 0);
    int nt = upd ? mi : d_tok[b];   // writer stores same value readers compute

    if (t < kT - 1) {
        float hnew;
        if (upd) {
            float4 a = *(const float4*)&d_xwx[((size_t)nt * kH + k) * 4];
            a.x += bias[k]; a.y += bias[kH + k]; a.z += bias[2 * kH + k]; a.w += bias[3 * kH + k];
#pragma unroll
            for (int hs = 0; hs < HS; hs++) {
                float4 p = *(const float4*)&d_gpart[(((size_t)hs * kB + b) * kH + k) * 4];
                a.x += p.x; a.y += p.y; a.z += p.z; a.w += p.w;
            }
            float c2 = sigf(a.y) * d_c[gid] + sigf(a.x) * tanhf(a.z);
            float h2 = sigf(a.w) * tanhf(c2);
            d_c[gid] = c2;
            d_hT[k * kB + b] = h2;
            hnew = h2;
        } else {
            hnew = d_hT[k * kB + b];
        }
        d_jointT[k * kB + b] = tanhf(tn[((size_t)b * kT + (t + 1)) * kH + k] + hnew);
    }

    if (k == 0) {
        float S = 0.f;
#pragma unroll
        for (int ch = 0; ch < BCH; ch++) S += d_bsum[b * BCH + ch];
        float val = m - logf(S);
        float sc = d_scores[b] + (upd ? val : 0.f);
        d_scores[b] = sc;
        if (t == kT - 1) out[b] = sc;
        out[kB + (size_t)b * kT + t] = (float)(upd ? mi : 0);
        if (upd) d_tok[b] = mi;
    }
}

// ---- one-time: xWx = embed @ Wx -> [v][k][gate] ----
__device__ void precompute_xwx(const float* __restrict__ embed, const float* __restrict__ Wx,
                               float (*sA)[20]) {
    for (int tp = blockIdx.x; tp < PTILES; tp += NBLK) {
        int rb = tp / 10, jch = tp % 10;
        int v0 = rb * 16;
        int j = jch * 256 + threadIdx.x;
        ull acc[8] = {0, 0, 0, 0, 0, 0, 0, 0};
        for (int hs = 0; hs < HS; hs++) {
            __syncthreads();
            fill_embed(sA, embed, v0, hs * DEP);
            __syncthreads();
            dot80(acc, sA, Wx + (size_t)(hs * DEP) * kG + j, kG);
        }
        int gate = j / kH, k = j - gate * kH;
#pragma unroll
        for (int i = 0; i < 8; i++) {
            float2 f = unpack2(acc[i]);
            int v = v0 + 2 * i;
            if (v < kV)     d_xwx[((size_t)v * kH + k) * 4 + gate] = f.x;
            if (v + 1 < kV) d_xwx[((size_t)(v + 1) * kH + k) * 4 + gate] = f.y;
        }
    }
}

// ---- init step: tok=0, h0=c0=0 -> h1,c1, joint(0) ----
__device__ void initC2(const float* __restrict__ tn, const float* __restrict__ bias) {
    int gid = blockIdx.x * NTHR + threadIdx.x;
    if (gid >= kB * kH) return;
    int b = gid / kH, k = gid - b * kH;
    float4 a = *(const float4*)&d_xwx[(size_t)k * 4];
    a.x += bias[k]; a.y += bias[kH + k]; a.z += bias[2 * kH + k]; a.w += bias[3 * kH + k];
    float c1 = sigf(a.x) * tanhf(a.z);
    float h1 = sigf(a.w) * tanhf(c1);
    d_c[gid] = c1;
    d_hT[k * kB + b] = h1;
    d_jointT[k * kB + b] = tanhf(tn[(size_t)b * kT * kH + k] + h1);
    if (k == 0) { d_scores[b] = 0.f; d_tok[b] = 0; }
}

__global__ void __launch_bounds__(NTHR, 4)
transducer_kernel(const float* __restrict__ tn, const float* __restrict__ embed,
                  const float* __restrict__ Wx, const float* __restrict__ Wh,
                  const float* __restrict__ bias, const float* __restrict__ Wc,
                  const float* __restrict__ bc, float* __restrict__ out) {
    __shared__ __align__(16) float sA[DEP][20];
    __shared__ float s_f[NTHR];
    __shared__ int   s_i[NTHR];
    __shared__ float s_s[NTHR];

    precompute_xwx(embed, Wx, sA);
    grid_barrier();
    initC2(tn, bias);
    grid_barrier();

    for (int t = 0; t < kT; ++t) {
        int pool = (t < kT - 1) ? POOL : TILES_A;
        for (int tt = blockIdx.x; tt < pool; tt += NBLK) {
            __syncthreads();
            gemm_tile(tt, sA, Wc, Wh);
            __syncthreads();
        }
        grid_barrier();
        phaseB(bc, s_f, s_i, s_s);
        grid_barrier();
        phaseC2(t, tn, bias, out);
        grid_barrier();
    }
}

extern "C" void kernel_launch(void* const* d_in, const int* in_sizes, int n_in,
                              void* d_out, int out_size) {
    const float* tn    = (const float*)d_in[0];
    const float* embed = (const float*)d_in[1];
    const float* Wx    = (const float*)d_in[2];
    const float* Wh    = (const float*)d_in[3];
    const float* bias  = (const float*)d_in[4];
    const float* Wc    = (const float*)d_in[5];
    const float* bc    = (const float*)d_in[6];
    float* out = (float*)d_out;
    (void)in_sizes; (void)n_in; (void)out_size;
    transducer_kernel<<<NBLK, NTHR>>>(tn, embed, Wx, Wh, bias, Wc, bc, out);
}

// round 6
// speedup vs baseline: 2.9074x; 1.1548x over previous
#include <cuda_runtime.h>

// Persistent single-kernel greedy transducer decode. B=32,T=1000,H=640,V=5000.
// Round 6: 2-col x 8-batch threads, 8-deep weight prefetch, B||CH overlap (compile fix).

typedef unsigned long long ull;

constexpr int kB = 32;
constexpr int kT = 1000;
constexpr int kH = 640;
constexpr int kV = 5000;
constexpr int kG = 2560;

constexpr int NBLK = 592;
constexpr int NTHR = 256;

constexpr int HS = 8, DEP = 80;
constexpr int TILES_A = 320;    // 10 vch(512) x 8 hs x 4 bg(8b)
constexpr int TILES_CH = 160;   // 5 jch(512) x 8 hs x 4 bg
constexpr int BCH = 8;          // 8 v-chunks of 640 -> 256 B-units
constexpr int PT = 3125;        // precompute: 625 rowblocks(8v) x 5 jch

// ---- device globals ----
__device__ __align__(16) float d_xwx[(size_t)kV * kH * 4];        // 51.2MB
__device__ __align__(16) float d_part[(size_t)HS * kB * kV];      // 5.12MB
__device__ __align__(16) float d_gpart[(size_t)HS * kB * kH * 4]; // 2.62MB
__device__ __align__(16) float d_jointT[kH * kB];                 // [k][b]
__device__ __align__(16) float d_hT[kH * kB];                     // [k][b]
__device__ __align__(16) float d_c[kB * kH];
__device__ float d_scores[kB];
__device__ int   d_tok[kB];
__device__ float d_bmax[kB * BCH];
__device__ int   d_bidx[kB * BCH];
__device__ float d_bsum[kB * BCH];
__device__ __align__(128) unsigned g_count[32];
__device__ __align__(128) unsigned g_gen[32];

__device__ __forceinline__ unsigned ld_cg(const unsigned* p) {
    unsigned v;
    asm volatile("ld.global.cg.u32 %0, [%1];" : "=r"(v) : "l"(p));
    return v;
}

__device__ __forceinline__ void grid_barrier() {
    __syncthreads();
    if (threadIdx.x == 0) {
        __threadfence();
        unsigned my = ld_cg(&g_gen[0]);
        if (atomicAdd(&g_count[0], 1u) == (unsigned)(NBLK - 1)) {
            atomicExch(&g_count[0], 0u);
            __threadfence();
            atomicAdd(&g_gen[0], 1u);
        } else {
            while (ld_cg(&g_gen[0]) == my) { __nanosleep(40); }
        }
        __threadfence();
    }
    __syncthreads();
}

// ---- f32x2 helpers ----
__device__ __forceinline__ ull pack2(float w) {
    ull r; asm("mov.b64 %0, {%1, %1};" : "=l"(r) : "f"(w)); return r;
}
__device__ __forceinline__ void ffma2(ull& a, ull s, ull w) {
    asm("fma.rn.f32x2 %0, %1, %2, %0;" : "+l"(a) : "l"(s), "l"(w));
}
__device__ __forceinline__ float2 unpack2(ull a) {
    float2 f; asm("mov.b64 {%0, %1}, %2;" : "=f"(f.x), "=f"(f.y) : "l"(a)); return f;
}
__device__ __forceinline__ float sigf(float x) { return 1.f / (1.f + expf(-x)); }

// 2-column x 8-batch dot over 80 depth rows. 8-row weight prefetch ring.
__device__ __forceinline__ void dot80_2(ull a1[4], ull a2[4], const float (*sA)[8],
                                        const float* __restrict__ w1p,
                                        const float* __restrict__ w2p, size_t ws) {
    float b1[8], b2[8];
#pragma unroll
    for (int j = 0; j < 8; j++) { b1[j] = w1p[j * ws]; b2[j] = w2p[j * ws]; }
    const float* f1 = w1p + 8 * ws;
    const float* f2 = w2p + 8 * ws;
#pragma unroll
    for (int g = 0; g < DEP; ++g) {
        float c1 = b1[g & 7], c2 = b2[g & 7];
        if (g < DEP - 8) { b1[g & 7] = *f1; f1 += ws; b2[g & 7] = *f2; f2 += ws; }
        ull W1 = pack2(c1), W2 = pack2(c2);
        const double2* sp = reinterpret_cast<const double2*>(sA[g]);
        double2 q0 = sp[0], q1 = sp[1];
        ull s0 = __double_as_longlong(q0.x);
        ull s1 = __double_as_longlong(q0.y);
        ull s2 = __double_as_longlong(q1.x);
        ull s3 = __double_as_longlong(q1.y);
        ffma2(a1[0], s0, W1); ffma2(a1[1], s1, W1);
        ffma2(a1[2], s2, W1); ffma2(a1[3], s3, W1);
        ffma2(a2[0], s0, W2); ffma2(a2[1], s1, W2);
        ffma2(a2[2], s2, W2); ffma2(a2[3], s3, W2);
    }
}

// Fill [80][8] tile from transposed [k][32] source (coalesced 32B chunks).
__device__ __forceinline__ void fill_T8(float (*dst)[8], const float* __restrict__ srcT,
                                        int bg, int hbase) {
    for (int idx = threadIdx.x; idx < DEP * 8; idx += NTHR) {
        int hh = idx >> 3, bb = idx & 7;
        dst[hh][bb] = srcT[(hbase + hh) * kB + bg * 8 + bb];
    }
}

// ---- A tile: jointT @ Wc -> d_part ----
__device__ void A_tile(int tt, float (*sA)[8], const float* __restrict__ Wc) {
    int hs = tt & 7, vch = (tt >> 3) % 10, bg = tt / 80;
    int hbase = hs * DEP;
    fill_T8(sA, d_jointT, bg, hbase);
    __syncthreads();
    int tid = threadIdx.x;
    int v1 = vch * 512 + tid;            // <= 4863, always valid
    int v2 = v1 + 256;
    bool ok2 = v2 < kV;
    const float* w1 = Wc + (size_t)hbase * kV + v1;
    const float* w2 = Wc + (size_t)hbase * kV + (ok2 ? v2 : v1);
    ull a1[4] = {0, 0, 0, 0}, a2[4] = {0, 0, 0, 0};
    dot80_2(a1, a2, sA, w1, w2, kV);
    size_t rb = (size_t)(hs * kB + bg * 8) * kV;
#pragma unroll
    for (int i = 0; i < 4; i++) {
        float2 f = unpack2(a1[i]);
        d_part[rb + (size_t)(2 * i) * kV + v1] = f.x;
        d_part[rb + (size_t)(2 * i + 1) * kV + v1] = f.y;
    }
    if (ok2) {
#pragma unroll
        for (int i = 0; i < 4; i++) {
            float2 f = unpack2(a2[i]);
            d_part[rb + (size_t)(2 * i) * kV + v2] = f.x;
            d_part[rb + (size_t)(2 * i + 1) * kV + v2] = f.y;
        }
    }
}

// ---- CH tile: hT @ Wh -> d_gpart ----
__device__ void CH_tile(int u, float (*sA)[8], const float* __restrict__ Wh) {
    int hs = u & 7, jch = (u >> 3) % 5, bg = u / 40;
    int hbase = hs * DEP;
    fill_T8(sA, d_hT, bg, hbase);
    __syncthreads();
    int tid = threadIdx.x;
    int j1 = jch * 512 + tid;
    int j2 = j1 + 256;
    const float* w1 = Wh + (size_t)hbase * kG + j1;
    const float* w2 = Wh + (size_t)hbase * kG + j2;
    ull a1[4] = {0, 0, 0, 0}, a2[4] = {0, 0, 0, 0};
    dot80_2(a1, a2, sA, w1, w2, kG);
    int g1 = j1 / kH, k1 = j1 - g1 * kH;
    int g2 = j2 / kH, k2 = j2 - g2 * kH;
#pragma unroll
    for (int i = 0; i < 4; i++) {
        float2 f = unpack2(a1[i]);
        d_gpart[(((size_t)hs * kB + bg * 8 + 2 * i) * kH + k1) * 4 + g1] = f.x;
        d_gpart[(((size_t)hs * kB + bg * 8 + 2 * i + 1) * kH + k1) * 4 + g1] = f.y;
    }
#pragma unroll
    for (int i = 0; i < 4; i++) {
        float2 f = unpack2(a2[i]);
        d_gpart[(((size_t)hs * kB + bg * 8 + 2 * i) * kH + k2) * 4 + g2] = f.x;
        d_gpart[(((size_t)hs * kB + bg * 8 + 2 * i + 1) * kH + k2) * 4 + g2] = f.y;
    }
}

// ---- phase B: per (b,chunk) argmax + sumexp over 640 v with float4 ----
__device__ void phaseB(const float* __restrict__ bc, float* s_f, int* s_i, float* s_s) {
    int u = blockIdx.x;
    int b = u >> 3, ch = u & 7;
    int v0 = ch * 640;
    int tid = threadIdx.x;

    float m = -1e30f; int mi = 0x7fffffff; float se = 0.f;
    int v = v0 + 4 * tid;
    if (tid < 160 && v < kV) {
        float4 s = *(const float4*)&bc[v];
#pragma unroll
        for (int hs = 0; hs < HS; hs++) {
            float4 p = *(const float4*)&d_part[((size_t)(hs * kB + b)) * kV + v];
            s.x += p.x; s.y += p.y; s.z += p.z; s.w += p.w;
        }
        se = expf(s.x) + expf(s.y) + expf(s.z) + expf(s.w);
        m = s.x; mi = v;
        if (s.y > m) { m = s.y; mi = v + 1; }
        if (s.z > m) { m = s.z; mi = v + 2; }
        if (s.w > m) { m = s.w; mi = v + 3; }
    }
    s_f[tid] = m; s_i[tid] = mi; s_s[tid] = se;
    __syncthreads();
    for (int w = 128; w; w >>= 1) {
        if (tid < w) {
            float om = s_f[tid + w]; int oi = s_i[tid + w];
            if (om > s_f[tid] || (om == s_f[tid] && oi < s_i[tid])) { s_f[tid] = om; s_i[tid] = oi; }
            s_s[tid] += s_s[tid + w];
        }
        __syncthreads();
    }
    if (tid == 0) { d_bmax[u] = s_f[0]; d_bidx[u] = s_i[0]; d_bsum[u] = s_s[0]; }
}

// ---- phase C2: combine + LSTM + next joint + emit ----
__device__ void phaseC2(int t, const float* __restrict__ tn, const float* __restrict__ bias,
                        float* __restrict__ out) {
    int gid = blockIdx.x * NTHR + threadIdx.x;
    if (gid >= kB * kH) return;
    int b = gid / kH, k = gid - b * kH;

    float m = -1e30f; int mi = 0;
#pragma unroll
    for (int ch = 0; ch < BCH; ch++) {
        float cm = d_bmax[b * BCH + ch];
        int ci = d_bidx[b * BCH + ch];
        if (cm > m) { m = cm; mi = ci; }
    }
    int upd = (mi != 0);
    int nt = upd ? mi : d_tok[b];

    if (t < kT - 1) {
        float hnew;
        if (upd) {
            float4 a = *(const float4*)&d_xwx[((size_t)nt * kH + k) * 4];
            a.x += bias[k]; a.y += bias[kH + k]; a.z += bias[2 * kH + k]; a.w += bias[3 * kH + k];
#pragma unroll
            for (int hs = 0; hs < HS; hs++) {
                float4 p = *(const float4*)&d_gpart[(((size_t)hs * kB + b) * kH + k) * 4];
                a.x += p.x; a.y += p.y; a.z += p.z; a.w += p.w;
            }
            float c2 = sigf(a.y) * d_c[gid] + sigf(a.x) * tanhf(a.z);
            float h2 = sigf(a.w) * tanhf(c2);
            d_c[gid] = c2;
            d_hT[k * kB + b] = h2;
            hnew = h2;
        } else {
            hnew = d_hT[k * kB + b];
        }
        d_jointT[k * kB + b] = tanhf(tn[((size_t)b * kT + (t + 1)) * kH + k] + hnew);
    }

    if (k == 0) {
        float S = 0.f;
#pragma unroll
        for (int ch = 0; ch < BCH; ch++) S += d_bsum[b * BCH + ch];
        float val = m - logf(S);
        float sc = d_scores[b] + (upd ? val : 0.f);
        d_scores[b] = sc;
        if (t == kT - 1) out[b] = sc;
        out[kB + (size_t)b * kT + t] = (float)(upd ? mi : 0);
        if (upd) d_tok[b] = mi;
    }
}

// ---- one-time: xWx = embed @ Wx -> [v][k][gate] ----
__device__ void precompute_xwx(const float* __restrict__ embed, const float* __restrict__ Wx,
                               float (*sA)[8]) {
    for (int tp = blockIdx.x; tp < PT; tp += NBLK) {
        int rb = tp / 5, jch = tp % 5;
        int v0 = rb * 8;
        int tid = threadIdx.x;
        int j1 = jch * 512 + tid, j2 = j1 + 256;
        ull a1[4] = {0, 0, 0, 0}, a2[4] = {0, 0, 0, 0};
        for (int hs = 0; hs < HS; hs++) {
            __syncthreads();
            for (int idx = tid; idx < DEP * 8; idx += NTHR) {
                int hh = idx >> 3, bb = idx & 7;
                sA[hh][bb] = embed[(size_t)(v0 + bb) * kH + hs * DEP + hh];
            }
            __syncthreads();
            dot80_2(a1, a2, sA, Wx + (size_t)(hs * DEP) * kG + j1,
                    Wx + (size_t)(hs * DEP) * kG + j2, kG);
        }
        int g1 = j1 / kH, k1 = j1 - g1 * kH;
        int g2 = j2 / kH, k2 = j2 - g2 * kH;
#pragma unroll
        for (int i = 0; i < 4; i++) {
            float2 f1 = unpack2(a1[i]);
            float2 f2 = unpack2(a2[i]);
            d_xwx[((size_t)(v0 + 2 * i) * kH + k1) * 4 + g1] = f1.x;
            d_xwx[((size_t)(v0 + 2 * i + 1) * kH + k1) * 4 + g1] = f1.y;
            d_xwx[((size_t)(v0 + 2 * i) * kH + k2) * 4 + g2] = f2.x;
            d_xwx[((size_t)(v0 + 2 * i + 1) * kH + k2) * 4 + g2] = f2.y;
        }
        __syncthreads();
    }
}

__device__ void initC2(const float* __restrict__ tn, const float* __restrict__ bias) {
    int gid = blockIdx.x * NTHR + threadIdx.x;
    if (gid >= kB * kH) return;
    int b = gid / kH, k = gid - b * kH;
    float4 a = *(const float4*)&d_xwx[(size_t)k * 4];
    a.x += bias[k]; a.y += bias[kH + k]; a.z += bias[2 * kH + k]; a.w += bias[3 * kH + k];
    float c1 = sigf(a.x) * tanhf(a.z);
    float h1 = sigf(a.w) * tanhf(c1);
    d_c[gid] = c1;
    d_hT[k * kB + b] = h1;
    d_jointT[k * kB + b] = tanhf(tn[(size_t)b * kT * kH + k] + h1);
    if (k == 0) { d_scores[b] = 0.f; d_tok[b] = 0; }
}

__global__ void __launch_bounds__(NTHR, 4)
transducer_kernel(const float* __restrict__ tn, const float* __restrict__ embed,
                  const float* __restrict__ Wx, const float* __restrict__ Wh,
                  const float* __restrict__ bias, const float* __restrict__ Wc,
                  const float* __restrict__ bc, float* __restrict__ out) {
    __shared__ __align__(16) float sA[DEP][8];
    __shared__ float s_f[NTHR];
    __shared__ int   s_i[NTHR];
    __shared__ float s_s[NTHR];

    precompute_xwx(embed, Wx, sA);
    grid_barrier();
    initC2(tn, bias);
    grid_barrier();

    for (int t = 0; t < kT; ++t) {
        if (blockIdx.x < TILES_A) A_tile(blockIdx.x, sA, Wc);
        grid_barrier();
        if (blockIdx.x < kB * BCH) {
            phaseB(bc, s_f, s_i, s_s);
        } else if (t < kT - 1 && blockIdx.x < kB * BCH + TILES_CH) {
            CH_tile(blockIdx.x - kB * BCH, sA, Wh);
        }
        grid_barrier();
        phaseC2(t, tn, bias, out);
        grid_barrier();
    }
}

extern "C" void kernel_launch(void* const* d_in, const int* in_sizes, int n_in,
                              void* d_out, int out_size) {
    const float* tn    = (const float*)d_in[0];
    const float* embed = (const float*)d_in[1];
    const float* Wx    = (const float*)d_in[2];
    const float* Wh    = (const float*)d_in[3];
    const float* bias  = (const float*)d_in[4];
    const float* Wc    = (const float*)d_in[5];
    const float* bc    = (const float*)d_in[6];
    float* out = (float*)d_out;
    (void)in_sizes; (void)n_in; (void)out_size;
    transducer_kernel<<<NBLK, NTHR>>>(tn, embed, Wx, Wh, bias, Wc, bc, out);
}